// round 2
// baseline (speedup 1.0000x reference)
#include <cuda_runtime.h>

#define NN 50000
#define DD 128
#define EE 800000
#define LN_EPS 1e-5f

// Scratch for support = A @ x  (25.6 MB)
__device__ float g_support[(size_t)NN * DD];

// ---------------------------------------------------------------------------
// Kernel 0: zero the scratch (float4 vectorized)
// ---------------------------------------------------------------------------
__global__ void zero_support_kernel() {
    size_t i = (size_t)blockIdx.x * blockDim.x + threadIdx.x;
    size_t n4 = (size_t)NN * DD / 4;
    if (i < n4) {
        ((float4*)g_support)[i] = make_float4(0.f, 0.f, 0.f, 0.f);
    }
}

// ---------------------------------------------------------------------------
// Kernel 1: COO SpMM scatter.  One warp per edge; lane q handles float4 q of
// the 128-float row.  support[row] += val * x[col].
// ---------------------------------------------------------------------------
__global__ void spmm_scatter_kernel(const float* __restrict__ x,
                                    const float* __restrict__ ev,
                                    const int* __restrict__ er,
                                    const int* __restrict__ ec) {
    size_t t = (size_t)blockIdx.x * blockDim.x + threadIdx.x;
    if (t >= (size_t)EE * 32) return;
    int e = (int)(t >> 5);
    int q = (int)(t & 31);
    int r = __ldg(er + e);
    int c = __ldg(ec + e);
    float v = __ldg(ev + e);
    float4 xv = ((const float4*)x)[(size_t)c * 32 + q];
    float* dst = g_support + (size_t)r * DD + q * 4;
    atomicAdd(dst + 0, v * xv.x);
    atomicAdd(dst + 1, v * xv.y);
    atomicAdd(dst + 2, v * xv.z);
    atomicAdd(dst + 3, v * xv.w);
}

// ---------------------------------------------------------------------------
// Kernel 2: h = support @ W^T + b ; LayerNorm ; ReLU.
// Persistent blocks of 128 threads. W stored transposed in smem with +1 pad
// (conflict-free both on store and on the per-k column read). 4-row register
// tile per iteration; LN via warp shuffle + smem cross-warp combine.
// ---------------------------------------------------------------------------
#define WT_STRIDE 129
#define SMEM_BYTES ((WT_STRIDE * 128 + 4 * 128 + 32) * 4)

__global__ __launch_bounds__(128) void gemm_ln_relu_kernel(
    const float* __restrict__ W,
    const float* __restrict__ bvec,
    const float* __restrict__ gamma,
    const float* __restrict__ beta,
    float* __restrict__ out) {
    extern __shared__ float smem[];
    float* Wt   = smem;                       // [128][129] : Wt[k*129+o] = W[o][k]
    float* srow = smem + WT_STRIDE * 128;     // [4][128]
    float* part = srow + 4 * 128;             // [4 rows][2 stats][4 warps]

    const int t    = threadIdx.x;
    const int lane = t & 31;
    const int wid  = t >> 5;

    // Load W transposed into smem. Coalesced gmem read; padded smem write.
    for (int idx = t; idx < 128 * 128; idx += 128) {
        int o = idx >> 7;
        int k = idx & 127;
        Wt[k * WT_STRIDE + o] = W[idx];
    }
    const float bias = bvec[t];
    const float g    = gamma[t];
    const float be   = beta[t];
    __syncthreads();

    const int ntiles = NN / 4;  // 12500, exact
    for (int tile = blockIdx.x; tile < ntiles; tile += gridDim.x) {
        const int row0 = tile * 4;
        __syncthreads();  // protect srow/part reuse from previous iteration

        // Load 4 support rows (512 floats) cooperatively as float4.
        ((float4*)srow)[t] = ((const float4*)(g_support + (size_t)row0 * DD))[t];
        __syncthreads();

        float a0 = bias, a1 = bias, a2 = bias, a3 = bias;
        const float* s0 = srow;
        const float* s1 = srow + 128;
        const float* s2 = srow + 256;
        const float* s3 = srow + 384;
#pragma unroll 16
        for (int k = 0; k < 128; k++) {
            float w = Wt[k * WT_STRIDE + t];
            a0 = fmaf(s0[k], w, a0);
            a1 = fmaf(s1[k], w, a1);
            a2 = fmaf(s2[k], w, a2);
            a3 = fmaf(s3[k], w, a3);
        }

        // --- LayerNorm reductions: sum and sumsq per row across 128 threads
        float v0 = a0, v1 = a1, v2 = a2, v3 = a3;
        float q0 = a0 * a0, q1 = a1 * a1, q2 = a2 * a2, q3 = a3 * a3;
#pragma unroll
        for (int o = 16; o > 0; o >>= 1) {
            v0 += __shfl_xor_sync(0xFFFFFFFFu, v0, o);
            v1 += __shfl_xor_sync(0xFFFFFFFFu, v1, o);
            v2 += __shfl_xor_sync(0xFFFFFFFFu, v2, o);
            v3 += __shfl_xor_sync(0xFFFFFFFFu, v3, o);
            q0 += __shfl_xor_sync(0xFFFFFFFFu, q0, o);
            q1 += __shfl_xor_sync(0xFFFFFFFFu, q1, o);
            q2 += __shfl_xor_sync(0xFFFFFFFFu, q2, o);
            q3 += __shfl_xor_sync(0xFFFFFFFFu, q3, o);
        }
        // part layout: part[row*8 + stat*4 + wid]
        if (lane == 0) {
            part[0 * 8 + 0 * 4 + wid] = v0;
            part[0 * 8 + 1 * 4 + wid] = q0;
            part[1 * 8 + 0 * 4 + wid] = v1;
            part[1 * 8 + 1 * 4 + wid] = q1;
            part[2 * 8 + 0 * 4 + wid] = v2;
            part[2 * 8 + 1 * 4 + wid] = q2;
            part[3 * 8 + 0 * 4 + wid] = v3;
            part[3 * 8 + 1 * 4 + wid] = q3;
        }
        __syncthreads();

        const float inv_d = 1.0f / 128.0f;
#pragma unroll
        for (int r = 0; r < 4; r++) {
            float sum = part[r * 8 + 0] + part[r * 8 + 1] + part[r * 8 + 2] + part[r * 8 + 3];
            float ssq = part[r * 8 + 4] + part[r * 8 + 5] + part[r * 8 + 6] + part[r * 8 + 7];
            float mu  = sum * inv_d;
            float var = ssq * inv_d - mu * mu;
            float rstd = rsqrtf(var + LN_EPS);
            float a = (r == 0) ? a0 : (r == 1) ? a1 : (r == 2) ? a2 : a3;
            float y = (a - mu) * rstd * g + be;
            out[(size_t)(row0 + r) * DD + t] = fmaxf(y, 0.0f);
        }
    }
}

// ---------------------------------------------------------------------------
extern "C" void kernel_launch(void* const* d_in, const int* in_sizes, int n_in,
                              void* d_out, int out_size) {
    const float* x     = (const float*)d_in[0];
    const float* ev    = (const float*)d_in[1];
    const float* W     = (const float*)d_in[2];
    const float* b     = (const float*)d_in[3];
    const float* gamma = (const float*)d_in[4];
    const float* beta  = (const float*)d_in[5];
    const int*   er    = (const int*)d_in[6];
    const int*   ec    = (const int*)d_in[7];
    float* out = (float*)d_out;

    (void)in_sizes; (void)n_in; (void)out_size;

    // 0) zero scratch
    {
        size_t n4 = (size_t)NN * DD / 4;
        int blocks = (int)((n4 + 255) / 256);
        zero_support_kernel<<<blocks, 256>>>();
    }
    // 1) COO scatter SpMM
    {
        size_t nt = (size_t)EE * 32;
        int blocks = (int)((nt + 255) / 256);
        spmm_scatter_kernel<<<blocks, 256>>>(x, ev, er, ec);
    }
    // 2) fused GEMM + bias + LayerNorm + ReLU
    {
        cudaFuncSetAttribute(gemm_ln_relu_kernel,
                             cudaFuncAttributeMaxDynamicSharedMemorySize,
                             SMEM_BYTES);
        gemm_ln_relu_kernel<<<444, 128, SMEM_BYTES>>>(W, b, gamma, beta, out);
    }
}

// round 3
// speedup vs baseline: 1.0057x; 1.0057x over previous
#include <cuda_runtime.h>

#define NN 50000
#define DD 128
#define EE 800000
#define LN_EPS 1e-5f

// CSR scratch
__device__ int   g_count[NN];
__device__ int   g_offset[NN + 1];
__device__ int   g_cursor[NN];
__device__ int   g_scol[EE];
__device__ float g_sval[EE];

// ---------------------------------------------------------------------------
// Kernel 0: zero row counts
// ---------------------------------------------------------------------------
__global__ void zero_counts_kernel() {
    int i = blockIdx.x * blockDim.x + threadIdx.x;
    if (i < NN) g_count[i] = 0;
}

// ---------------------------------------------------------------------------
// Kernel 1: histogram of edge rows
// ---------------------------------------------------------------------------
__global__ void hist_kernel(const int* __restrict__ er) {
    int e = blockIdx.x * blockDim.x + threadIdx.x;
    if (e < EE) atomicAdd(&g_count[__ldg(er + e)], 1);
}

// ---------------------------------------------------------------------------
// Kernel 2: exclusive prefix scan over 50K counts (single block, two-pass)
// ---------------------------------------------------------------------------
#define SCAN_T 1024
#define SCAN_CHUNK 49  // 1024*49 = 50176 >= 50000

__global__ __launch_bounds__(SCAN_T) void scan_kernel() {
    __shared__ int ssum[SCAN_T];
    const int tid  = threadIdx.x;
    const int base = tid * SCAN_CHUNK;

    // pass 1: per-thread chunk sum
    int s = 0;
#pragma unroll
    for (int i = 0; i < SCAN_CHUNK; i++) {
        int idx = base + i;
        s += (idx < NN) ? g_count[idx] : 0;
    }
    ssum[tid] = s;
    __syncthreads();

    // inclusive Hillis-Steele scan over 1024 partials
    for (int off = 1; off < SCAN_T; off <<= 1) {
        int v = 0;
        if (tid >= off) v = ssum[tid - off];
        __syncthreads();
        if (tid >= off) ssum[tid] += v;
        __syncthreads();
    }

    // pass 2: write exclusive offsets (and cursor copy)
    int run = (tid > 0) ? ssum[tid - 1] : 0;
#pragma unroll
    for (int i = 0; i < SCAN_CHUNK; i++) {
        int idx = base + i;
        if (idx < NN) {
            g_offset[idx] = run;
            g_cursor[idx] = run;
            run += g_count[idx];
        }
    }
    if (tid == SCAN_T - 1) g_offset[NN] = ssum[SCAN_T - 1];
}

// ---------------------------------------------------------------------------
// Kernel 3: permute edges into row-sorted order
// ---------------------------------------------------------------------------
__global__ void edge_sort_kernel(const float* __restrict__ ev,
                                 const int* __restrict__ er,
                                 const int* __restrict__ ec) {
    int e = blockIdx.x * blockDim.x + threadIdx.x;
    if (e >= EE) return;
    int r = __ldg(er + e);
    int p = atomicAdd(&g_cursor[r], 1);
    g_scol[p] = __ldg(ec + e);
    g_sval[p] = __ldg(ev + e);
}

// ---------------------------------------------------------------------------
// Kernel 4: fused gather-SpMM + GEMM + bias + LayerNorm + ReLU.
// 128 threads/block. Per 4-row tile: warp w gathers row row0+w into registers
// (lane holds float4 chunk), writes smem; then register-tiled GEMM + LN.
// ---------------------------------------------------------------------------
#define WT_STRIDE 129
#define SMEM_BYTES ((WT_STRIDE * 128 + 4 * 128 + 32) * 4)

__global__ __launch_bounds__(128) void fused_kernel(
    const float* __restrict__ x,
    const float* __restrict__ W,
    const float* __restrict__ bvec,
    const float* __restrict__ gamma,
    const float* __restrict__ beta,
    float* __restrict__ out) {
    extern __shared__ float smem[];
    float* Wt   = smem;                       // [128][129] : Wt[k*129+o] = W[o][k]
    float* srow = smem + WT_STRIDE * 128;     // [4][128]
    float* part = srow + 4 * 128;             // [4 rows][2 stats][4 warps]

    const int t    = threadIdx.x;
    const int lane = t & 31;
    const int wid  = t >> 5;

    // Load W transposed into smem (coalesced read, padded write).
    for (int idx = t; idx < 128 * 128; idx += 128) {
        int o = idx >> 7;
        int k = idx & 127;
        Wt[k * WT_STRIDE + o] = W[idx];
    }
    const float bias = bvec[t];
    const float g    = gamma[t];
    const float be   = beta[t];
    __syncthreads();

    const int ntiles = NN / 4;  // 12500
    for (int tile = blockIdx.x; tile < ntiles; tile += gridDim.x) {
        const int row0 = tile * 4;
        __syncthreads();  // srow/part from previous iteration fully consumed

        // --- gather phase: warp `wid` accumulates row row0+wid ---
        {
            const int row = row0 + wid;
            const int beg = __ldg(&g_offset[row]);
            const int end = __ldg(&g_offset[row + 1]);
            float4 acc = make_float4(0.f, 0.f, 0.f, 0.f);
            int e = beg;
            for (; e + 1 < end; e += 2) {
                int   c0 = g_scol[e];
                int   c1 = g_scol[e + 1];
                float v0 = g_sval[e];
                float v1 = g_sval[e + 1];
                float4 x0 = ((const float4*)x)[(size_t)c0 * 32 + lane];
                float4 x1 = ((const float4*)x)[(size_t)c1 * 32 + lane];
                acc.x = fmaf(v0, x0.x, acc.x); acc.y = fmaf(v0, x0.y, acc.y);
                acc.z = fmaf(v0, x0.z, acc.z); acc.w = fmaf(v0, x0.w, acc.w);
                acc.x = fmaf(v1, x1.x, acc.x); acc.y = fmaf(v1, x1.y, acc.y);
                acc.z = fmaf(v1, x1.z, acc.z); acc.w = fmaf(v1, x1.w, acc.w);
            }
            if (e < end) {
                int   c0 = g_scol[e];
                float v0 = g_sval[e];
                float4 x0 = ((const float4*)x)[(size_t)c0 * 32 + lane];
                acc.x = fmaf(v0, x0.x, acc.x); acc.y = fmaf(v0, x0.y, acc.y);
                acc.z = fmaf(v0, x0.z, acc.z); acc.w = fmaf(v0, x0.w, acc.w);
            }
            ((float4*)srow)[wid * 32 + lane] = acc;
        }
        __syncthreads();

        // --- GEMM phase: h[row0+r][t] = bias + sum_k srow[r][k] * W[t][k] ---
        float a0 = bias, a1 = bias, a2 = bias, a3 = bias;
        const float* s0 = srow;
        const float* s1 = srow + 128;
        const float* s2 = srow + 256;
        const float* s3 = srow + 384;
#pragma unroll 16
        for (int k = 0; k < 128; k++) {
            float w = Wt[k * WT_STRIDE + t];
            a0 = fmaf(s0[k], w, a0);
            a1 = fmaf(s1[k], w, a1);
            a2 = fmaf(s2[k], w, a2);
            a3 = fmaf(s3[k], w, a3);
        }

        // --- LayerNorm reductions ---
        float v0 = a0, v1 = a1, v2 = a2, v3 = a3;
        float q0 = a0 * a0, q1 = a1 * a1, q2 = a2 * a2, q3 = a3 * a3;
#pragma unroll
        for (int o = 16; o > 0; o >>= 1) {
            v0 += __shfl_xor_sync(0xFFFFFFFFu, v0, o);
            v1 += __shfl_xor_sync(0xFFFFFFFFu, v1, o);
            v2 += __shfl_xor_sync(0xFFFFFFFFu, v2, o);
            v3 += __shfl_xor_sync(0xFFFFFFFFu, v3, o);
            q0 += __shfl_xor_sync(0xFFFFFFFFu, q0, o);
            q1 += __shfl_xor_sync(0xFFFFFFFFu, q1, o);
            q2 += __shfl_xor_sync(0xFFFFFFFFu, q2, o);
            q3 += __shfl_xor_sync(0xFFFFFFFFu, q3, o);
        }
        if (lane == 0) {
            part[0 * 8 + 0 * 4 + wid] = v0;
            part[0 * 8 + 1 * 4 + wid] = q0;
            part[1 * 8 + 0 * 4 + wid] = v1;
            part[1 * 8 + 1 * 4 + wid] = q1;
            part[2 * 8 + 0 * 4 + wid] = v2;
            part[2 * 8 + 1 * 4 + wid] = q2;
            part[3 * 8 + 0 * 4 + wid] = v3;
            part[3 * 8 + 1 * 4 + wid] = q3;
        }
        __syncthreads();

        const float inv_d = 1.0f / 128.0f;
#pragma unroll
        for (int r = 0; r < 4; r++) {
            float sum = part[r * 8 + 0] + part[r * 8 + 1] + part[r * 8 + 2] + part[r * 8 + 3];
            float ssq = part[r * 8 + 4] + part[r * 8 + 5] + part[r * 8 + 6] + part[r * 8 + 7];
            float mu  = sum * inv_d;
            float var = ssq * inv_d - mu * mu;
            float rstd = rsqrtf(var + LN_EPS);
            float a = (r == 0) ? a0 : (r == 1) ? a1 : (r == 2) ? a2 : a3;
            float y = (a - mu) * rstd * g + be;
            out[(size_t)(row0 + r) * DD + t] = fmaxf(y, 0.0f);
        }
    }
}

// ---------------------------------------------------------------------------
extern "C" void kernel_launch(void* const* d_in, const int* in_sizes, int n_in,
                              void* d_out, int out_size) {
    const float* x     = (const float*)d_in[0];
    const float* ev    = (const float*)d_in[1];
    const float* W     = (const float*)d_in[2];
    const float* b     = (const float*)d_in[3];
    const float* gamma = (const float*)d_in[4];
    const float* beta  = (const float*)d_in[5];
    const int*   er    = (const int*)d_in[6];
    const int*   ec    = (const int*)d_in[7];
    float* out = (float*)d_out;

    (void)in_sizes; (void)n_in; (void)out_size;

    zero_counts_kernel<<<(NN + 255) / 256, 256>>>();
    hist_kernel<<<(EE + 255) / 256, 256>>>(er);
    scan_kernel<<<1, SCAN_T>>>();
    edge_sort_kernel<<<(EE + 255) / 256, 256>>>(ev, er, ec);

    cudaFuncSetAttribute(fused_kernel,
                         cudaFuncAttributeMaxDynamicSharedMemorySize,
                         SMEM_BYTES);
    fused_kernel<<<444, 128, SMEM_BYTES>>>(x, W, b, gamma, beta, out);
}

// round 5
// speedup vs baseline: 1.5656x; 1.5568x over previous
#include <cuda_runtime.h>

#define NN 50000
#define DD 128
#define EE 800000
#define LN_EPS 1e-5f
#define FULLM 0xFFFFFFFFu

// CSR + support scratch
__device__ int   g_count[NN];
__device__ int   g_offset[NN + 1];
__device__ int   g_cursor[NN];
__device__ int   g_scol[EE];
__device__ float g_sval[EE];
__device__ float g_support[(size_t)NN * DD];

// ---------------------------------------------------------------------------
// Kernel 0: zero row counts
// ---------------------------------------------------------------------------
__global__ void zero_counts_kernel() {
    int i = blockIdx.x * blockDim.x + threadIdx.x;
    if (i < NN) g_count[i] = 0;
}

// ---------------------------------------------------------------------------
// Kernel 1: histogram of edge rows
// ---------------------------------------------------------------------------
__global__ void hist_kernel(const int* __restrict__ er) {
    int e = blockIdx.x * blockDim.x + threadIdx.x;
    if (e < EE) atomicAdd(&g_count[__ldg(er + e)], 1);
}

// ---------------------------------------------------------------------------
// Kernel 2: exclusive prefix scan over 50K counts (single block, two-pass)
// ---------------------------------------------------------------------------
#define SCAN_T 1024
#define SCAN_CHUNK 49  // 1024*49 = 50176 >= 50000

__global__ __launch_bounds__(SCAN_T) void scan_kernel() {
    __shared__ int ssum[SCAN_T];
    const int tid  = threadIdx.x;
    const int base = tid * SCAN_CHUNK;

    int s = 0;
#pragma unroll
    for (int i = 0; i < SCAN_CHUNK; i++) {
        int idx = base + i;
        s += (idx < NN) ? g_count[idx] : 0;
    }
    ssum[tid] = s;
    __syncthreads();

    for (int off = 1; off < SCAN_T; off <<= 1) {
        int v = 0;
        if (tid >= off) v = ssum[tid - off];
        __syncthreads();
        if (tid >= off) ssum[tid] += v;
        __syncthreads();
    }

    int run = (tid > 0) ? ssum[tid - 1] : 0;
#pragma unroll
    for (int i = 0; i < SCAN_CHUNK; i++) {
        int idx = base + i;
        if (idx < NN) {
            g_offset[idx] = run;
            g_cursor[idx] = run;
            run += g_count[idx];
        }
    }
    if (tid == SCAN_T - 1) g_offset[NN] = ssum[SCAN_T - 1];
}

// ---------------------------------------------------------------------------
// Kernel 3: permute edges into row-sorted order
// ---------------------------------------------------------------------------
__global__ void edge_sort_kernel(const float* __restrict__ ev,
                                 const int* __restrict__ er,
                                 const int* __restrict__ ec) {
    int e = blockIdx.x * blockDim.x + threadIdx.x;
    if (e >= EE) return;
    int r = __ldg(er + e);
    int p = atomicAdd(&g_cursor[r], 1);
    g_scol[p] = __ldg(ec + e);
    g_sval[p] = __ldg(ev + e);
}

// ---------------------------------------------------------------------------
// Kernel 4: CSR gather SpMM. One warp per row; lane holds one float4 chunk.
// Coalesced edge loads + shfl broadcast; x-row loads unrolled 4-wide for MLP.
// ---------------------------------------------------------------------------
__global__ __launch_bounds__(256) void spmm_gather_kernel(const float* __restrict__ x) {
    const int lane = threadIdx.x & 31;
    const int row  = (blockIdx.x * blockDim.x + threadIdx.x) >> 5;
    if (row >= NN) return;

    const int beg = __ldg(&g_offset[row]);
    const int end = __ldg(&g_offset[row + 1]);
    float4 acc = make_float4(0.f, 0.f, 0.f, 0.f);

    for (int gb = beg; gb < end; gb += 32) {
        const int n = min(32, end - gb);
        int   cc = 0;
        float vv = 0.f;
        if (gb + lane < end) {
            cc = __ldg(&g_scol[gb + lane]);
            vv = __ldg(&g_sval[gb + lane]);
        }
        int j = 0;
        for (; j + 4 <= n; j += 4) {
            int   c0 = __shfl_sync(FULLM, cc, j);
            int   c1 = __shfl_sync(FULLM, cc, j + 1);
            int   c2 = __shfl_sync(FULLM, cc, j + 2);
            int   c3 = __shfl_sync(FULLM, cc, j + 3);
            float v0 = __shfl_sync(FULLM, vv, j);
            float v1 = __shfl_sync(FULLM, vv, j + 1);
            float v2 = __shfl_sync(FULLM, vv, j + 2);
            float v3 = __shfl_sync(FULLM, vv, j + 3);
            float4 x0 = __ldg(&((const float4*)x)[(size_t)c0 * 32 + lane]);
            float4 x1 = __ldg(&((const float4*)x)[(size_t)c1 * 32 + lane]);
            float4 x2 = __ldg(&((const float4*)x)[(size_t)c2 * 32 + lane]);
            float4 x3 = __ldg(&((const float4*)x)[(size_t)c3 * 32 + lane]);
            acc.x = fmaf(v0, x0.x, acc.x); acc.y = fmaf(v0, x0.y, acc.y);
            acc.z = fmaf(v0, x0.z, acc.z); acc.w = fmaf(v0, x0.w, acc.w);
            acc.x = fmaf(v1, x1.x, acc.x); acc.y = fmaf(v1, x1.y, acc.y);
            acc.z = fmaf(v1, x1.z, acc.z); acc.w = fmaf(v1, x1.w, acc.w);
            acc.x = fmaf(v2, x2.x, acc.x); acc.y = fmaf(v2, x2.y, acc.y);
            acc.z = fmaf(v2, x2.z, acc.z); acc.w = fmaf(v2, x2.w, acc.w);
            acc.x = fmaf(v3, x3.x, acc.x); acc.y = fmaf(v3, x3.y, acc.y);
            acc.z = fmaf(v3, x3.z, acc.z); acc.w = fmaf(v3, x3.w, acc.w);
        }
        for (; j < n; j++) {
            int   c0 = __shfl_sync(FULLM, cc, j);
            float v0 = __shfl_sync(FULLM, vv, j);
            float4 x0 = __ldg(&((const float4*)x)[(size_t)c0 * 32 + lane]);
            acc.x = fmaf(v0, x0.x, acc.x); acc.y = fmaf(v0, x0.y, acc.y);
            acc.z = fmaf(v0, x0.z, acc.z); acc.w = fmaf(v0, x0.w, acc.w);
        }
    }
    ((float4*)g_support)[(size_t)row * 32 + lane] = acc;
}

// ---------------------------------------------------------------------------
// Kernel 5: GEMM v2 + bias + LayerNorm + ReLU.
// 128 threads, tile = 16 rows x 128 cols. Warp w owns rows 4w..4w+3; lane owns
// cols 4*lane..4*lane+3. Support enters via coalesced LDG + shfl broadcast
// (no broadcast LDS); W read as one LDS.128 per k per thread.
// ---------------------------------------------------------------------------
#define WT_S 132
#define SMEM_BYTES (WT_S * 128 * 4)
#define NTILES (NN / 16)  // 3125

__global__ __launch_bounds__(128) void gemm_ln_relu_v2(
    const float* __restrict__ W,
    const float* __restrict__ bvec,
    const float* __restrict__ gamma,
    const float* __restrict__ beta,
    float* __restrict__ out) {
    extern __shared__ float Wt[];  // [128 k][132 stride] : Wt[k*132+c] = W[c][k]

    const int t    = threadIdx.x;
    const int lane = t & 31;
    const int wid  = t >> 5;
    const int c0   = 4 * lane;

    // Load W transposed (coalesced gmem read; one-time smem write conflicts OK)
    for (int idx = t; idx < 128 * 128; idx += 128) {
        int c = idx >> 7;
        int k = idx & 127;
        Wt[k * WT_S + c] = W[idx];
    }
    const float4 bias = ((const float4*)bvec)[lane];
    const float4 gmv  = ((const float4*)gamma)[lane];
    const float4 btv  = ((const float4*)beta)[lane];
    __syncthreads();

    for (int tile = blockIdx.x; tile < NTILES; tile += gridDim.x) {
        const int row0 = tile * 16 + wid * 4;  // this warp's 4 rows
        const float* sr = g_support + (size_t)row0 * DD;

        float acc[4][4];
#pragma unroll
        for (int r = 0; r < 4; r++) {
            acc[r][0] = bias.x; acc[r][1] = bias.y;
            acc[r][2] = bias.z; acc[r][3] = bias.w;
        }

        // stage k-group 0 (coalesced: lane l gets s[row][l])
        float sA = __ldg(sr + lane);
        float sB = __ldg(sr + 128 + lane);
        float sC = __ldg(sr + 256 + lane);
        float sD = __ldg(sr + 384 + lane);

#pragma unroll
        for (int g = 0; g < 4; g++) {
            const int k0 = g * 32;
            float nA = 0.f, nB = 0.f, nC = 0.f, nD = 0.f;
            if (g < 3) {
                nA = __ldg(sr + k0 + 32 + lane);
                nB = __ldg(sr + 128 + k0 + 32 + lane);
                nC = __ldg(sr + 256 + k0 + 32 + lane);
                nD = __ldg(sr + 384 + k0 + 32 + lane);
            }
#pragma unroll
            for (int j = 0; j < 32; j++) {
                float v0 = __shfl_sync(FULLM, sA, j);
                float v1 = __shfl_sync(FULLM, sB, j);
                float v2 = __shfl_sync(FULLM, sC, j);
                float v3 = __shfl_sync(FULLM, sD, j);
                float4 wv = *(const float4*)&Wt[(k0 + j) * WT_S + c0];
                acc[0][0] = fmaf(v0, wv.x, acc[0][0]);
                acc[0][1] = fmaf(v0, wv.y, acc[0][1]);
                acc[0][2] = fmaf(v0, wv.z, acc[0][2]);
                acc[0][3] = fmaf(v0, wv.w, acc[0][3]);
                acc[1][0] = fmaf(v1, wv.x, acc[1][0]);
                acc[1][1] = fmaf(v1, wv.y, acc[1][1]);
                acc[1][2] = fmaf(v1, wv.z, acc[1][2]);
                acc[1][3] = fmaf(v1, wv.w, acc[1][3]);
                acc[2][0] = fmaf(v2, wv.x, acc[2][0]);
                acc[2][1] = fmaf(v2, wv.y, acc[2][1]);
                acc[2][2] = fmaf(v2, wv.z, acc[2][2]);
                acc[2][3] = fmaf(v2, wv.w, acc[2][3]);
                acc[3][0] = fmaf(v3, wv.x, acc[3][0]);
                acc[3][1] = fmaf(v3, wv.y, acc[3][1]);
                acc[3][2] = fmaf(v3, wv.z, acc[3][2]);
                acc[3][3] = fmaf(v3, wv.w, acc[3][3]);
            }
            sA = nA; sB = nB; sC = nC; sD = nD;
        }

        // LayerNorm + ReLU per row (each row lives entirely in this warp)
#pragma unroll
        for (int r = 0; r < 4; r++) {
            float s = acc[r][0] + acc[r][1] + acc[r][2] + acc[r][3];
            float q = acc[r][0] * acc[r][0] + acc[r][1] * acc[r][1]
                    + acc[r][2] * acc[r][2] + acc[r][3] * acc[r][3];
#pragma unroll
            for (int o = 16; o > 0; o >>= 1) {
                s += __shfl_xor_sync(FULLM, s, o);
                q += __shfl_xor_sync(FULLM, q, o);
            }
            const float mu   = s * (1.0f / 128.0f);
            const float var  = q * (1.0f / 128.0f) - mu * mu;
            const float rstd = rsqrtf(var + LN_EPS);
            float4 y;
            y.x = fmaxf((acc[r][0] - mu) * rstd * gmv.x + btv.x, 0.f);
            y.y = fmaxf((acc[r][1] - mu) * rstd * gmv.y + btv.y, 0.f);
            y.z = fmaxf((acc[r][2] - mu) * rstd * gmv.z + btv.z, 0.f);
            y.w = fmaxf((acc[r][3] - mu) * rstd * gmv.w + btv.w, 0.f);
            ((float4*)out)[(size_t)(row0 + r) * 32 + lane] = y;
        }
    }
}

// ---------------------------------------------------------------------------
extern "C" void kernel_launch(void* const* d_in, const int* in_sizes, int n_in,
                              void* d_out, int out_size) {
    const float* x     = (const float*)d_in[0];
    const float* ev    = (const float*)d_in[1];
    const float* W     = (const float*)d_in[2];
    const float* b     = (const float*)d_in[3];
    const float* gamma = (const float*)d_in[4];
    const float* beta  = (const float*)d_in[5];
    const int*   er    = (const int*)d_in[6];
    const int*   ec    = (const int*)d_in[7];
    float* out = (float*)d_out;

    (void)in_sizes; (void)n_in; (void)out_size;

    zero_counts_kernel<<<(NN + 255) / 256, 256>>>();
    hist_kernel<<<(EE + 255) / 256, 256>>>(er);
    scan_kernel<<<1, SCAN_T>>>();
    edge_sort_kernel<<<(EE + 255) / 256, 256>>>(ev, er, ec);

    // gather: one warp per row
    spmm_gather_kernel<<<(NN * 32 + 255) / 256, 256>>>(x);

    cudaFuncSetAttribute(gemm_ln_relu_v2,
                         cudaFuncAttributeMaxDynamicSharedMemorySize,
                         SMEM_BYTES);
    gemm_ln_relu_v2<<<444, 128, SMEM_BYTES>>>(W, b, gamma, beta, out);
}